// round 4
// baseline (speedup 1.0000x reference)
#include <cuda_runtime.h>
#include <math.h>

typedef unsigned long long ULL;
typedef unsigned int U32;

#define NB 2
#define NS 2048
#define NE 1024
#define NH 16
#define NHD 64
#define NM 4096                  // NB*NS
#define ATT_SCALE (1.0f/32.0f)   // 1/sqrt(1024), exact power of two

// ---------------- scratch (device globals; no allocation allowed) ----------
__device__ float g_q[NB*NH*NS*NHD];    // head-major: [b*16+h][s][hd]
__device__ float g_k[NB*NH*NS*NHD];
__device__ float g_v[NB*NH*NS*NHD];
__device__ float g_ctx[NB*NH*NS*NHD];
__device__ float g_cos[NS*32];
__device__ float g_sin[NS*32];

// ---------------- packed f32x2 helpers (flash attention path) --------------
__device__ __forceinline__ ULL pk2(float lo, float hi){
    ULL r; unsigned a=__float_as_uint(lo), b=__float_as_uint(hi);
    asm("mov.b64 %0, {%1,%2};" : "=l"(r) : "r"(a), "r"(b));
    return r;
}
__device__ __forceinline__ void up2(ULL v, float& lo, float& hi){
    unsigned a,b;
    asm("mov.b64 {%0,%1}, %2;" : "=r"(a), "=r"(b) : "l"(v));
    lo=__uint_as_float(a); hi=__uint_as_float(b);
}
__device__ __forceinline__ void fma2(ULL& d, ULL a, ULL b){
    asm("fma.rn.f32x2 %0, %1, %2, %0;" : "+l"(d) : "l"(a), "l"(b));
}
__device__ __forceinline__ ULL mul2(ULL a, ULL b){
    ULL d; asm("mul.rn.f32x2 %0, %1, %2;" : "=l"(d) : "l"(a), "l"(b));
    return d;
}

// ---------------- tf32 mma.sync helpers (NOT 'a'-gated; works on sm_103) ---
__device__ __forceinline__ U32 f2tf(float x){
    U32 u; asm("cvt.rn.tf32.f32 %0, %1;" : "=r"(u) : "f"(x)); return u;
}
__device__ __forceinline__ void mma8(float* c, const U32* a, const U32* b){
    asm volatile("mma.sync.aligned.m16n8k8.row.col.f32.tf32.tf32.f32 "
        "{%0,%1,%2,%3}, {%4,%5,%6,%7}, {%8,%9}, {%0,%1,%2,%3};"
        : "+f"(c[0]), "+f"(c[1]), "+f"(c[2]), "+f"(c[3])
        : "r"(a[0]), "r"(a[1]), "r"(a[2]), "r"(a[3]), "r"(b[0]), "r"(b[1]));
}

// ---------------- tf32 tensor GEMM: C[m,n] = sum_e A[m,e] * W[n,e] ---------
// M=4096, N=1024, K=1024. CTA tile 128x128, BK=32, 256 thr = 8 warps (2x4),
// warp tile 64x32 via m16n8k8: 4 m-frags x 4 n-frags.
#define GBK 32
#define GSW 136                    // smem row width (U32), pad 8 -> frag loads conflict-free

__global__ void __launch_bounds__(256, 2)
gemm_mma(const float* __restrict__ A, const float* __restrict__ Wt,
         float* __restrict__ C, int a_heads, int c_heads)
{
    __shared__ U32 As[GBK][GSW];   // [k][m]
    __shared__ U32 Bs[GBK][GSW];   // [k][n]

    const int t    = threadIdx.x;
    const int lane = t & 31;
    const int wid  = t >> 5;
    const int wm   = (wid & 1) * 64;     // warp row offset (2 warp-rows)
    const int wn   = (wid >> 1) * 32;    // warp col offset (4 warp-cols)
    const int grp  = lane >> 2;          // 0..7
    const int tig  = lane & 3;           // 0..3
    const int bm   = blockIdx.y * 128;
    const int bn   = blockIdx.x * 128;

    // global load mapping: each thread owns 16 consecutive e of one row
    const int lrow  = t >> 1;            // 0..127
    const int lhalf = (t & 1) * 16;      // 0 or 16

    float acc[4][4][4];
    #pragma unroll
    for (int i=0;i<4;++i)
        #pragma unroll
        for (int j=0;j<4;++j)
            #pragma unroll
            for (int r=0;r<4;++r) acc[i][j][r] = 0.0f;

    for (int kt = 0; kt < NE/GBK; ++kt) {
        const int k0 = kt * GBK;
        const int e0 = k0 + lhalf;
        // ---- global -> regs ----
        const float* pa;
        {
            int m = bm + lrow;
            if (!a_heads) pa = A + (size_t)m*NE + e0;
            else {
                int b = m >> 11, s = m & 2047;
                pa = A + ((size_t)((b*16 + (e0>>6))*NS + s))*64 + (e0 & 63);
            }
        }
        const float* pb = Wt + (size_t)(bn + lrow)*NE + e0;
        float4 fa0 = *(const float4*)(pa+0),  fa1 = *(const float4*)(pa+4);
        float4 fa2 = *(const float4*)(pa+8),  fa3 = *(const float4*)(pa+12);
        float4 fb0 = *(const float4*)(pb+0),  fb1 = *(const float4*)(pb+4);
        float4 fb2 = *(const float4*)(pb+8),  fb3 = *(const float4*)(pb+12);

        __syncthreads();                 // previous iter fully consumed
        {
            float av[16] = {fa0.x,fa0.y,fa0.z,fa0.w, fa1.x,fa1.y,fa1.z,fa1.w,
                            fa2.x,fa2.y,fa2.z,fa2.w, fa3.x,fa3.y,fa3.z,fa3.w};
            float bv[16] = {fb0.x,fb0.y,fb0.z,fb0.w, fb1.x,fb1.y,fb1.z,fb1.w,
                            fb2.x,fb2.y,fb2.z,fb2.w, fb3.x,fb3.y,fb3.z,fb3.w};
            #pragma unroll
            for (int j = 0; j < 16; ++j) {
                As[lhalf + j][lrow] = f2tf(av[j]);
                Bs[lhalf + j][lrow] = f2tf(bv[j]);
            }
        }
        __syncthreads();

        // ---- mma: 4 k-steps of 8 ----
        #pragma unroll
        for (int ks = 0; ks < 4; ++ks) {
            const int kk = ks * 8;
            U32 af[4][4];
            #pragma unroll
            for (int mf = 0; mf < 4; ++mf) {
                int mr = wm + mf*16;
                af[mf][0] = As[kk + tig    ][mr + grp    ];
                af[mf][1] = As[kk + tig    ][mr + grp + 8];
                af[mf][2] = As[kk + tig + 4][mr + grp    ];
                af[mf][3] = As[kk + tig + 4][mr + grp + 8];
            }
            U32 bf[4][2];
            #pragma unroll
            for (int nf = 0; nf < 4; ++nf) {
                int nc = wn + nf*8;
                bf[nf][0] = Bs[kk + tig    ][nc + grp];
                bf[nf][1] = Bs[kk + tig + 4][nc + grp];
            }
            #pragma unroll
            for (int mf = 0; mf < 4; ++mf)
                #pragma unroll
                for (int nf = 0; nf < 4; ++nf)
                    mma8(acc[mf][nf], af[mf], bf[nf]);
        }
    }

    // ---- epilogue ----
    #pragma unroll
    for (int mf = 0; mf < 4; ++mf) {
        #pragma unroll
        for (int half = 0; half < 2; ++half) {
            int m = bm + wm + mf*16 + grp + half*8;
            #pragma unroll
            for (int nf = 0; nf < 4; ++nf) {
                int n = bn + wn + nf*8 + 2*tig;
                float2 f;
                f.x = acc[mf][nf][half*2 + 0];
                f.y = acc[mf][nf][half*2 + 1];
                if (!c_heads) {
                    *(float2*)(C + (size_t)m*NE + n) = f;
                } else {
                    int b = m >> 11, s = m & 2047;
                    *(float2*)(C + ((size_t)((b*16 + (n>>6))*NS + s))*64 + (n & 63)) = f;
                }
            }
        }
    }
}

// ---------------- RoPE table + apply ---------------------------------------
__global__ void rope_table_kernel()
{
    int idx = blockIdx.x * blockDim.x + threadIdx.x;   // 65536
    if (idx >= NS*32) return;
    int s = idx >> 5, p = idx & 31;
    double invf = 1.0 / pow(10000.0, (double)(2*p) / 64.0);
    double a = (double)s * invf;
    g_cos[idx] = (float)cos(a);
    g_sin[idx] = (float)sin(a);
}

__global__ void rope_apply_kernel(float* __restrict__ x)
{
    int t = blockIdx.x * blockDim.x + threadIdx.x;     // pair index
    if (t >= NB*NH*NS*32) return;
    int sp = t & (NS*32 - 1);                          // s*32 + p (per bh)
    float c = g_cos[sp], s = g_sin[sp];
    float2 v = *(float2*)(x + (size_t)t*2);
    float2 o;
    o.x = v.x*c - v.y*s;
    o.y = v.x*s + v.y*c;
    *(float2*)(x + (size_t)t*2) = o;
}

// ---------------- Flash attention (fp32, shifted-causal mask) --------------
#define FL_SMEM_FLOATS (64*66 + 64*65 + 64*65 + 64*66)
#define FL_SMEM_BYTES  (FL_SMEM_FLOATS*4)

__global__ void __launch_bounds__(128, 3)
flash_attn_kernel()
{
    extern __shared__ __align__(16) float sm[];
    float* Qt = sm;                       // [d][r] stride 66 (Q^T, pre-scaled)
    float* Ks = Qt + 64*66;               // [c][d] stride 65
    float* Vs = Ks + 64*65;               // [c][d] stride 65
    float* Pt = Vs + 64*65;               // [c][r] stride 66

    const int t  = threadIdx.x;
    const int tx = t & 15;                // col group (4 cols)
    const int ty = t >> 4;                // row group (8 rows)
    const int bh = blockIdx.y;
    const int qb = (int)gridDim.x - 1 - (int)blockIdx.x;   // heavy tiles first
    const int q0 = qb * 64;

    const float* qp = g_q + (size_t)bh * NS * 64;
    const float* kp = g_k + (size_t)bh * NS * 64;
    const float* vp = g_v + (size_t)bh * NS * 64;

    #pragma unroll
    for (int it = 0; it < 8; ++it) {
        int i4  = it*128 + t;             // 1024 float4
        int row = i4 >> 4, c4 = i4 & 15;
        float4 f = *(const float4*)(qp + (size_t)(q0+row)*64 + c4*4);
        int d = c4*4;
        Qt[(d+0)*66 + row] = f.x * ATT_SCALE;
        Qt[(d+1)*66 + row] = f.y * ATT_SCALE;
        Qt[(d+2)*66 + row] = f.z * ATT_SCALE;
        Qt[(d+3)*66 + row] = f.w * ATT_SCALE;
    }

    float m_r[8], l_r[8];
    #pragma unroll
    for (int r=0;r<8;++r){ m_r[r] = -1e30f; l_r[r] = 0.0f; }
    ULL ctx2[4][4];                       // [row-pair][d-col]
    #pragma unroll
    for (int i=0;i<4;++i)
        #pragma unroll
        for (int j=0;j<4;++j) ctx2[i][j] = 0ULL;

    for (int kb = 0; kb <= qb; ++kb) {
        const int k0 = kb * 64;
        #pragma unroll
        for (int it = 0; it < 8; ++it) {
            int i4  = it*128 + t;
            int row = i4 >> 4, c4 = i4 & 15;
            float4 f = *(const float4*)(kp + (size_t)(k0+row)*64 + c4*4);
            float* kd = &Ks[row*65 + c4*4];
            kd[0]=f.x; kd[1]=f.y; kd[2]=f.z; kd[3]=f.w;
            float4 g = *(const float4*)(vp + (size_t)(k0+row)*64 + c4*4);
            float* vd = &Vs[row*65 + c4*4];
            vd[0]=g.x; vd[1]=g.y; vd[2]=g.z; vd[3]=g.w;
        }
        __syncthreads();

        // S = (Q*scale) @ K^T ; row-paired f32x2
        ULL s2[4][4];
        #pragma unroll
        for (int i=0;i<4;++i)
            #pragma unroll
            for (int c=0;c<4;++c) s2[i][c] = 0ULL;
        #pragma unroll 8
        for (int d = 0; d < 64; ++d) {
            const ULL* qq = (const ULL*)&Qt[d*66 + ty*8];
            ULL a0=qq[0], a1=qq[1], a2=qq[2], a3=qq[3];
            #pragma unroll
            for (int c=0;c<4;++c) {
                float kv = Ks[(tx*4+c)*65 + d];
                ULL k2 = pk2(kv, kv);
                fma2(s2[0][c], a0, k2);
                fma2(s2[1][c], a1, k2);
                fma2(s2[2][c], a2, k2);
                fma2(s2[3][c], a3, k2);
            }
        }

        // online softmax + write P^T
        #pragma unroll
        for (int i=0;i<4;++i) {
            float v_[2][4];
            #pragma unroll
            for (int c=0;c<4;++c) up2(s2[i][c], v_[0][c], v_[1][c]);
            float fac2[2];
            #pragma unroll
            for (int l=0;l<2;++l) {
                int r  = 2*i + l;
                int gi = q0 + ty*8 + r;
                float rm = -1e30f;
                #pragma unroll
                for (int c=0;c<4;++c) {
                    int gj = k0 + tx*4 + c;
                    float s = v_[l][c];
                    if (gj >= gi && !(gi == 0 && gj == 0)) s = -1e30f;
                    v_[l][c] = s;
                    rm = fmaxf(rm, s);
                }
                #pragma unroll
                for (int off=1; off<16; off<<=1)
                    rm = fmaxf(rm, __shfl_xor_sync(0xffffffffu, rm, off));
                float mnew = fmaxf(m_r[r], rm);
                float fac  = expf(m_r[r] - mnew);
                float ps = 0.0f;
                #pragma unroll
                for (int c=0;c<4;++c) {
                    float p = expf(v_[l][c] - mnew);
                    Pt[(tx*4+c)*66 + ty*8 + r] = p;
                    ps += p;
                }
                #pragma unroll
                for (int off=1; off<16; off<<=1)
                    ps += __shfl_xor_sync(0xffffffffu, ps, off);
                l_r[r] = l_r[r]*fac + ps;
                m_r[r] = mnew;
                fac2[l] = fac;
            }
            ULL ff = pk2(fac2[0], fac2[1]);
            #pragma unroll
            for (int j=0;j<4;++j) ctx2[i][j] = mul2(ctx2[i][j], ff);
        }
        __syncthreads();

        // ctx += P @ V ; row-paired f32x2
        #pragma unroll 8
        for (int c = 0; c < 64; ++c) {
            const ULL* pp = (const ULL*)&Pt[c*66 + ty*8];
            ULL p0=pp[0], p1=pp[1], p2=pp[2], p3=pp[3];
            #pragma unroll
            for (int j=0;j<4;++j) {
                float vv = Vs[c*65 + tx*4 + j];
                ULL v2 = pk2(vv, vv);
                fma2(ctx2[0][j], p0, v2);
                fma2(ctx2[1][j], p1, v2);
                fma2(ctx2[2][j], p2, v2);
                fma2(ctx2[3][j], p3, v2);
            }
        }
        __syncthreads();
    }

    // normalize + write ctx (head-major)
    float* op = g_ctx + (size_t)bh * NS * 64;
    #pragma unroll
    for (int i=0;i<4;++i) {
        float lo[4], hi[4];
        #pragma unroll
        for (int j=0;j<4;++j) up2(ctx2[i][j], lo[j], hi[j]);
        #pragma unroll
        for (int l=0;l<2;++l) {
            float* o = l ? hi : lo;
            int r = 2*i + l;
            float inv = 1.0f / l_r[r];
            float4 f = make_float4(o[0]*inv, o[1]*inv, o[2]*inv, o[3]*inv);
            *(float4*)(op + (size_t)(q0 + ty*8 + r)*64 + tx*4) = f;
        }
    }
}

// ---------------------------------------------------------------------------
extern "C" void kernel_launch(void* const* d_in, const int* in_sizes, int n_in,
                              void* d_out, int out_size)
{
    const float* q  = (const float*)d_in[0];
    const float* k  = (const float*)d_in[1];
    const float* v  = (const float*)d_in[2];
    const float* Wq = (const float*)d_in[3];
    const float* Wk = (const float*)d_in[4];
    const float* Wv = (const float*)d_in[5];
    const float* Wo = (const float*)d_in[6];
    float* out = (float*)d_out;

    float *pq, *pk, *pv, *pctx;
    cudaGetSymbolAddress((void**)&pq,   g_q);
    cudaGetSymbolAddress((void**)&pk,   g_k);
    cudaGetSymbolAddress((void**)&pv,   g_v);
    cudaGetSymbolAddress((void**)&pctx, g_ctx);

    cudaFuncSetAttribute(flash_attn_kernel,
                         cudaFuncAttributeMaxDynamicSharedMemorySize,
                         FL_SMEM_BYTES);

    rope_table_kernel<<<256, 256>>>();

    dim3 gg(NE/128, NM/128);               // (8, 32)
    gemm_mma<<<gg, 256>>>(q, Wq, pq, 0, 1);
    gemm_mma<<<gg, 256>>>(k, Wk, pk, 0, 1);
    gemm_mma<<<gg, 256>>>(v, Wv, pv, 0, 1);

    int npair = NB*NH*NS*32;
    rope_apply_kernel<<<(npair+255)/256, 256>>>(pq);
    rope_apply_kernel<<<(npair+255)/256, 256>>>(pk);

    dim3 fg(NS/64, NB*NH);                 // (32, 32)
    flash_attn_kernel<<<fg, 128, FL_SMEM_BYTES>>>();

    gemm_mma<<<gg, 256>>>(pctx, Wo, out, 1, 0);
}

// round 5
// speedup vs baseline: 2.0361x; 2.0361x over previous
#include <cuda_runtime.h>
#include <math.h>

typedef unsigned long long ULL;
typedef unsigned int U32;

#define NB 2
#define NS 2048
#define NE 1024
#define NH 16
#define NHD 64
#define NM 4096                  // NB*NS
#define ATT_SCALE (1.0f/32.0f)   // 1/sqrt(1024), exact power of two

// ---------------- scratch (device globals; no allocation allowed) ----------
__device__ float g_q[NB*NH*NS*NHD];    // head-major: [b*16+h][s][hd]
__device__ float g_k[NB*NH*NS*NHD];
__device__ float g_v[NB*NH*NS*NHD];
__device__ float g_ctx[NB*NH*NS*NHD];
__device__ float g_cos[NS*32];
__device__ float g_sin[NS*32];

// ---------------- tf32 mma.sync helpers (works on plain sm_103) ------------
__device__ __forceinline__ U32 f2tf(float x){
    U32 u; asm("cvt.rn.tf32.f32 %0, %1;" : "=r"(u) : "f"(x)); return u;
}
__device__ __forceinline__ void mma8(float* c, const U32* a, const U32* b){
    asm volatile("mma.sync.aligned.m16n8k8.row.col.f32.tf32.tf32.f32 "
        "{%0,%1,%2,%3}, {%4,%5,%6,%7}, {%8,%9}, {%0,%1,%2,%3};"
        : "+f"(c[0]), "+f"(c[1]), "+f"(c[2]), "+f"(c[3])
        : "r"(a[0]), "r"(a[1]), "r"(a[2]), "r"(a[3]), "r"(b[0]), "r"(b[1]));
}

// ---------------- tf32 tensor GEMM: C[m,n] = sum_e A[m,e] * W[n,e] ---------
// M=4096, N=1024, K=1024. CTA tile 128x128, BK=32, 256 thr = 8 warps (2x4),
// warp tile 64x32 via m16n8k8: 4 m-frags x 4 n-frags.  (proven in R4)
#define GBK 32
#define GSW 136

__global__ void __launch_bounds__(256, 2)
gemm_mma(const float* __restrict__ A, const float* __restrict__ Wt,
         float* __restrict__ C, int a_heads, int c_heads)
{
    __shared__ U32 As[GBK][GSW];   // [k][m]
    __shared__ U32 Bs[GBK][GSW];   // [k][n]

    const int t    = threadIdx.x;
    const int lane = t & 31;
    const int wid  = t >> 5;
    const int wm   = (wid & 1) * 64;
    const int wn   = (wid >> 1) * 32;
    const int grp  = lane >> 2;
    const int tig  = lane & 3;
    const int bm   = blockIdx.y * 128;
    const int bn   = blockIdx.x * 128;

    const int lrow  = t >> 1;
    const int lhalf = (t & 1) * 16;

    float acc[4][4][4];
    #pragma unroll
    for (int i=0;i<4;++i)
        #pragma unroll
        for (int j=0;j<4;++j)
            #pragma unroll
            for (int r=0;r<4;++r) acc[i][j][r] = 0.0f;

    for (int kt = 0; kt < NE/GBK; ++kt) {
        const int k0 = kt * GBK;
        const int e0 = k0 + lhalf;
        const float* pa;
        {
            int m = bm + lrow;
            if (!a_heads) pa = A + (size_t)m*NE + e0;
            else {
                int b = m >> 11, s = m & 2047;
                pa = A + ((size_t)((b*16 + (e0>>6))*NS + s))*64 + (e0 & 63);
            }
        }
        const float* pb = Wt + (size_t)(bn + lrow)*NE + e0;
        float4 fa0 = *(const float4*)(pa+0),  fa1 = *(const float4*)(pa+4);
        float4 fa2 = *(const float4*)(pa+8),  fa3 = *(const float4*)(pa+12);
        float4 fb0 = *(const float4*)(pb+0),  fb1 = *(const float4*)(pb+4);
        float4 fb2 = *(const float4*)(pb+8),  fb3 = *(const float4*)(pb+12);

        __syncthreads();
        {
            float av[16] = {fa0.x,fa0.y,fa0.z,fa0.w, fa1.x,fa1.y,fa1.z,fa1.w,
                            fa2.x,fa2.y,fa2.z,fa2.w, fa3.x,fa3.y,fa3.z,fa3.w};
            float bv[16] = {fb0.x,fb0.y,fb0.z,fb0.w, fb1.x,fb1.y,fb1.z,fb1.w,
                            fb2.x,fb2.y,fb2.z,fb2.w, fb3.x,fb3.y,fb3.z,fb3.w};
            #pragma unroll
            for (int j = 0; j < 16; ++j) {
                As[lhalf + j][lrow] = f2tf(av[j]);
                Bs[lhalf + j][lrow] = f2tf(bv[j]);
            }
        }
        __syncthreads();

        #pragma unroll
        for (int ks = 0; ks < 4; ++ks) {
            const int kk = ks * 8;
            U32 af[4][4];
            #pragma unroll
            for (int mf = 0; mf < 4; ++mf) {
                int mr = wm + mf*16;
                af[mf][0] = As[kk + tig    ][mr + grp    ];
                af[mf][1] = As[kk + tig    ][mr + grp + 8];
                af[mf][2] = As[kk + tig + 4][mr + grp    ];
                af[mf][3] = As[kk + tig + 4][mr + grp + 8];
            }
            U32 bf[4][2];
            #pragma unroll
            for (int nf = 0; nf < 4; ++nf) {
                int nc = wn + nf*8;
                bf[nf][0] = Bs[kk + tig    ][nc + grp];
                bf[nf][1] = Bs[kk + tig + 4][nc + grp];
            }
            #pragma unroll
            for (int mf = 0; mf < 4; ++mf)
                #pragma unroll
                for (int nf = 0; nf < 4; ++nf)
                    mma8(acc[mf][nf], af[mf], bf[nf]);
        }
    }

    #pragma unroll
    for (int mf = 0; mf < 4; ++mf) {
        #pragma unroll
        for (int half = 0; half < 2; ++half) {
            int m = bm + wm + mf*16 + grp + half*8;
            #pragma unroll
            for (int nf = 0; nf < 4; ++nf) {
                int n = bn + wn + nf*8 + 2*tig;
                float2 f;
                f.x = acc[mf][nf][half*2 + 0];
                f.y = acc[mf][nf][half*2 + 1];
                if (!c_heads) {
                    *(float2*)(C + (size_t)m*NE + n) = f;
                } else {
                    int b = m >> 11, s = m & 2047;
                    *(float2*)(C + ((size_t)((b*16 + (n>>6))*NS + s))*64 + (n & 63)) = f;
                }
            }
        }
    }
}

// ---------------- RoPE table + apply ---------------------------------------
__global__ void rope_table_kernel()
{
    int idx = blockIdx.x * blockDim.x + threadIdx.x;   // 65536
    if (idx >= NS*32) return;
    int s = idx >> 5, p = idx & 31;
    double invf = 1.0 / pow(10000.0, (double)(2*p) / 64.0);
    double a = (double)s * invf;
    g_cos[idx] = (float)cos(a);
    g_sin[idx] = (float)sin(a);
}

__global__ void rope_apply_kernel(float* __restrict__ x)
{
    int t = blockIdx.x * blockDim.x + threadIdx.x;     // pair index
    if (t >= NB*NH*NS*32) return;
    int sp = t & (NS*32 - 1);
    float c = g_cos[sp], s = g_sin[sp];
    float2 v = *(float2*)(x + (size_t)t*2);
    float2 o;
    o.x = v.x*c - v.y*s;
    o.y = v.x*s + v.y*c;
    *(float2*)(x + (size_t)t*2) = o;
}

// ---------------- Flash attention with tf32 mma.sync -----------------------
// Tile: 64 q-rows x 64 kv. 128 thr = 4 warps; warp = 16 q-rows.
// All smem operands tf32 (U32), stride 72 (==8 mod 32 -> conflict-free frags).
#define FSW 72
#define FL_BYTES (4*64*FSW*4)      // Qs, Ks, Vs, Ps = 73728 B

__global__ void __launch_bounds__(128)
flash_mma_kernel()
{
    extern __shared__ __align__(16) U32 sm[];
    U32* Qs = sm;                  // [d][r]  (Q^T, pre-scaled, tf32)
    U32* Ks = sm + 64*FSW;         // [d][c]  (K^T, tf32)
    U32* Vs = sm + 2*64*FSW;       // [c][d]  (tf32)
    U32* Ps = sm + 3*64*FSW;       // [c][r]  (P^T, tf32)

    const int t    = threadIdx.x;
    const int lane = t & 31;
    const int wid  = t >> 5;
    const int grp  = lane >> 2;          // 0..7
    const int tig  = lane & 3;           // 0..3
    const int wr   = wid * 16;           // warp's q-row base within tile
    const int bh   = blockIdx.y;
    const int qb   = (int)gridDim.x - 1 - (int)blockIdx.x;  // heavy first
    const int q0   = qb * 64;

    const float* qp = g_q + (size_t)bh * NS * 64;
    const float* kp = g_k + (size_t)bh * NS * 64;
    const float* vp = g_v + (size_t)bh * NS * 64;

    // load Q tile -> Qs[d][r], scaled+tf32
    #pragma unroll
    for (int it = 0; it < 8; ++it) {
        int i4  = it*128 + t;            // 1024 float4
        int row = i4 >> 4, c4 = i4 & 15;
        float4 f = *(const float4*)(qp + (size_t)(q0+row)*64 + c4*4);
        int d = c4*4;
        Qs[(d+0)*FSW + row] = f2tf(f.x * ATT_SCALE);
        Qs[(d+1)*FSW + row] = f2tf(f.y * ATT_SCALE);
        Qs[(d+2)*FSW + row] = f2tf(f.z * ATT_SCALE);
        Qs[(d+3)*FSW + row] = f2tf(f.w * ATT_SCALE);
    }

    float m_[2], l_[2];
    m_[0] = m_[1] = -1e30f;
    l_[0] = l_[1] = 0.0f;
    float octx[8][4];
    #pragma unroll
    for (int nf=0;nf<8;++nf)
        #pragma unroll
        for (int r=0;r<4;++r) octx[nf][r] = 0.0f;

    for (int kb = 0; kb <= qb; ++kb) {
        const int k0 = kb * 64;
        if (kb) __syncthreads();         // prev PV done before overwrite
        #pragma unroll
        for (int it = 0; it < 8; ++it) {
            int i4  = it*128 + t;
            int row = i4 >> 4, c4 = i4 & 15;
            float4 f = *(const float4*)(kp + (size_t)(k0+row)*64 + c4*4);
            int d = c4*4;
            Ks[(d+0)*FSW + row] = f2tf(f.x);
            Ks[(d+1)*FSW + row] = f2tf(f.y);
            Ks[(d+2)*FSW + row] = f2tf(f.z);
            Ks[(d+3)*FSW + row] = f2tf(f.w);
            float4 g = *(const float4*)(vp + (size_t)(k0+row)*64 + c4*4);
            uint4 u;
            u.x=f2tf(g.x); u.y=f2tf(g.y); u.z=f2tf(g.z); u.w=f2tf(g.w);
            *(uint4*)(&Vs[row*FSW + d]) = u;
        }
        __syncthreads();

        // ---- S = (Q*scale) @ K^T : 8 k-steps, 8 n-frags ----
        float sacc[8][4];
        #pragma unroll
        for (int nf=0;nf<8;++nf)
            #pragma unroll
            for (int r=0;r<4;++r) sacc[nf][r] = 0.0f;
        #pragma unroll
        for (int ks = 0; ks < 8; ++ks) {
            const int kk = ks * 8;
            U32 af[4];
            af[0] = Qs[(kk + tig    )*FSW + wr + grp    ];
            af[1] = Qs[(kk + tig    )*FSW + wr + grp + 8];
            af[2] = Qs[(kk + tig + 4)*FSW + wr + grp    ];
            af[3] = Qs[(kk + tig + 4)*FSW + wr + grp + 8];
            #pragma unroll
            for (int nf = 0; nf < 8; ++nf) {
                U32 bf[2];
                bf[0] = Ks[(kk + tig    )*FSW + nf*8 + grp];
                bf[1] = Ks[(kk + tig + 4)*FSW + nf*8 + grp];
                mma8(sacc[nf], af, bf);
            }
        }

        // ---- online softmax (2 rows per thread) ----
        const bool diag = (kb == qb);
        #pragma unroll
        for (int l = 0; l < 2; ++l) {
            const int rloc = wr + grp + 8*l;     // row within tile
            const int gi   = q0 + rloc;
            float rm = -1e30f;
            #pragma unroll
            for (int nf = 0; nf < 8; ++nf) {
                #pragma unroll
                for (int c = 0; c < 2; ++c) {
                    float s = sacc[nf][2*l + c];
                    if (diag) {
                        int gj = k0 + nf*8 + 2*tig + c;
                        if (gj >= gi && !(gi == 0 && gj == 0)) s = -1e30f;
                    }
                    sacc[nf][2*l + c] = s;
                    rm = fmaxf(rm, s);
                }
            }
            rm = fmaxf(rm, __shfl_xor_sync(0xffffffffu, rm, 1));
            rm = fmaxf(rm, __shfl_xor_sync(0xffffffffu, rm, 2));
            float mnew = fmaxf(m_[l], rm);
            float fac  = __expf(m_[l] - mnew);
            float ps = 0.0f;
            #pragma unroll
            for (int nf = 0; nf < 8; ++nf) {
                #pragma unroll
                for (int c = 0; c < 2; ++c) {
                    float p = __expf(sacc[nf][2*l + c] - mnew);
                    Ps[(nf*8 + 2*tig + c)*FSW + rloc] = f2tf(p);
                    ps += p;
                }
            }
            ps += __shfl_xor_sync(0xffffffffu, ps, 1);
            ps += __shfl_xor_sync(0xffffffffu, ps, 2);
            l_[l] = l_[l]*fac + ps;
            m_[l] = mnew;
            #pragma unroll
            for (int nf = 0; nf < 8; ++nf) {
                octx[nf][2*l + 0] *= fac;
                octx[nf][2*l + 1] *= fac;
            }
        }
        __syncwarp();                    // P^T smem visible within warp

        // ---- ctx += P @ V : 8 k-steps over kv, 8 n-frags over hd ----
        #pragma unroll
        for (int ks = 0; ks < 8; ++ks) {
            const int kk = ks * 8;
            U32 af[4];
            af[0] = Ps[(kk + tig    )*FSW + wr + grp    ];
            af[1] = Ps[(kk + tig    )*FSW + wr + grp + 8];
            af[2] = Ps[(kk + tig + 4)*FSW + wr + grp    ];
            af[3] = Ps[(kk + tig + 4)*FSW + wr + grp + 8];
            #pragma unroll
            for (int nf = 0; nf < 8; ++nf) {
                U32 bf[2];
                bf[0] = Vs[(kk + tig    )*FSW + nf*8 + grp];
                bf[1] = Vs[(kk + tig + 4)*FSW + nf*8 + grp];
                mma8(octx[nf], af, bf);
            }
        }
    }

    // ---- normalize + write ctx (head-major) ----
    float* op = g_ctx + (size_t)bh * NS * 64;
    #pragma unroll
    for (int l = 0; l < 2; ++l) {
        const int r  = q0 + wr + grp + 8*l;
        const float inv = 1.0f / l_[l];
        #pragma unroll
        for (int nf = 0; nf < 8; ++nf) {
            float2 f;
            f.x = octx[nf][2*l + 0] * inv;
            f.y = octx[nf][2*l + 1] * inv;
            *(float2*)(op + (size_t)r*64 + nf*8 + 2*tig) = f;
        }
    }
}

// ---------------------------------------------------------------------------
extern "C" void kernel_launch(void* const* d_in, const int* in_sizes, int n_in,
                              void* d_out, int out_size)
{
    const float* q  = (const float*)d_in[0];
    const float* k  = (const float*)d_in[1];
    const float* v  = (const float*)d_in[2];
    const float* Wq = (const float*)d_in[3];
    const float* Wk = (const float*)d_in[4];
    const float* Wv = (const float*)d_in[5];
    const float* Wo = (const float*)d_in[6];
    float* out = (float*)d_out;

    float *pq, *pk, *pv, *pctx;
    cudaGetSymbolAddress((void**)&pq,   g_q);
    cudaGetSymbolAddress((void**)&pk,   g_k);
    cudaGetSymbolAddress((void**)&pv,   g_v);
    cudaGetSymbolAddress((void**)&pctx, g_ctx);

    cudaFuncSetAttribute(flash_mma_kernel,
                         cudaFuncAttributeMaxDynamicSharedMemorySize,
                         FL_BYTES);

    rope_table_kernel<<<256, 256>>>();

    dim3 gg(NE/128, NM/128);               // (8, 32)
    gemm_mma<<<gg, 256>>>(q, Wq, pq, 0, 1);
    gemm_mma<<<gg, 256>>>(k, Wk, pk, 0, 1);
    gemm_mma<<<gg, 256>>>(v, Wv, pv, 0, 1);

    int npair = NB*NH*NS*32;
    rope_apply_kernel<<<(npair+255)/256, 256>>>(pq);
    rope_apply_kernel<<<(npair+255)/256, 256>>>(pk);

    dim3 fg(NS/64, NB*NH);                 // (32, 32)
    flash_mma_kernel<<<fg, 128, FL_BYTES>>>();

    gemm_mma<<<gg, 256>>>(pctx, Wo, out, 1, 0);
}